// round 3
// baseline (speedup 1.0000x reference)
#include <cuda_runtime.h>
#include <cuda_bf16.h>
#include <cstdint>

#define N_ATOMS 10000
#define N_PAIRS 250000
#define NPROP   128

typedef unsigned long long u64;

// ---------------- f32x2 packed helpers (sm_100+) ----------------
__device__ __forceinline__ u64 pk2(float lo, float hi) {
    u64 r; asm("mov.b64 %0,{%1,%2};" : "=l"(r) : "f"(lo), "f"(hi)); return r;
}
__device__ __forceinline__ void upk2(u64 v, float& lo, float& hi) {
    asm("mov.b64 {%0,%1},%2;" : "=f"(lo), "=f"(hi) : "l"(v));
}
__device__ __forceinline__ u64 add2(u64 a, u64 b) {
    u64 r; asm("add.rn.f32x2 %0,%1,%2;" : "=l"(r) : "l"(a), "l"(b)); return r;
}
__device__ __forceinline__ u64 mul2(u64 a, u64 b) {
    u64 r; asm("mul.rn.f32x2 %0,%1,%2;" : "=l"(r) : "l"(a), "l"(b)); return r;
}
__device__ __forceinline__ u64 fma2(u64 a, u64 b, u64 c) {
    u64 r; asm("fma.rn.f32x2 %0,%1,%2,%3;" : "=l"(r) : "l"(a), "l"(b), "l"(c)); return r;
}

// ---------------- device scratch (static, allocation-free) ----------------
__device__ int   g_counts[N_ATOMS];
__device__ int   g_cursor[N_ATOMS];
__device__ int   g_offsets[N_ATOMS + 1];
__device__ int   g_pairlist[N_PAIRS];
__device__ float g_pxacc[(size_t)N_ATOMS * 3 * NPROP];

// ---------------- K0: zero counts / cursors ----------------
__global__ void k_init() {
    int t = blockIdx.x * blockDim.x + threadIdx.x;
    if (t < N_ATOMS) { g_counts[t] = 0; g_cursor[t] = 0; }
}

// ---------------- K1: histogram of ind_i ----------------
__global__ void k_hist(const int* __restrict__ ind2) {
    int p = blockIdx.x * blockDim.x + threadIdx.x;
    if (p < N_PAIRS) atomicAdd(&g_counts[ind2[2 * p]], 1);
}

// ---------------- K2: exclusive scan of counts -> offsets (1 block) -------
__global__ void k_scan() {
    __shared__ int part[1024];
    const int PER = 10;
    int t = threadIdx.x;
    int local[PER];
    int sum = 0;
#pragma unroll
    for (int r = 0; r < PER; r++) {
        int idx = t * PER + r;
        int v = (idx < N_ATOMS) ? g_counts[idx] : 0;
        local[r] = sum;
        sum += v;
    }
    part[t] = sum;
    __syncthreads();
    for (int off = 1; off < 1024; off <<= 1) {
        int v = (t >= off) ? part[t - off] : 0;
        __syncthreads();
        part[t] += v;
        __syncthreads();
    }
    int base = (t > 0) ? part[t - 1] : 0;
#pragma unroll
    for (int r = 0; r < PER; r++) {
        int idx = t * PER + r;
        if (idx < N_ATOMS) g_offsets[idx] = base + local[r];
    }
    if (t == 1023) g_offsets[N_ATOMS] = part[1023];
}

// ---------------- K3: scatter pair ids into CSR ----------------
__global__ void k_scatter(const int* __restrict__ ind2) {
    int p = blockIdx.x * blockDim.x + threadIdx.x;
    if (p < N_PAIRS) {
        int i = ind2[2 * p];
        int pos = atomicAdd(&g_cursor[i], 1);
        g_pairlist[g_offsets[i] + pos] = p;
    }
}

// ---------------- K3b: per-segment sort (deterministic sum order) ---------
__global__ void k_sort() {
    int a = blockIdx.x * blockDim.x + threadIdx.x;
    if (a >= N_ATOMS) return;
    int s = g_offsets[a], e = g_offsets[a + 1];
    for (int i = s + 1; i < e; i++) {
        int v = g_pairlist[i];
        int j = i - 1;
        while (j >= s && g_pairlist[j] > v) { g_pairlist[j + 1] = g_pairlist[j]; j--; }
        g_pairlist[j + 1] = v;
    }
}

// ---------------- K4: hot kernel — ix + per-atom segment sum --------------
// One warp per atom; lane owns 4 channels. ix = (px_j + diff)*i1, streamed
// with __stcs. f32x2 packed math halves fp instruction count. Next-pair
// indices (pairlist entry + ind_j) are prefetched to break the serial
// pairlist->ind2->px dependency chain.
__global__ void __launch_bounds__(128) k_accum(
        const int*   __restrict__ ind2,
        const float* __restrict__ px,
        const float* __restrict__ i1,
        const float* __restrict__ diff,
        float*       __restrict__ ix) {
    int wd   = threadIdx.x >> 5;
    int lane = threadIdx.x & 31;
    int a = blockIdx.x * 4 + wd;              // grid = N_ATOMS/4 exactly
    int s = g_offsets[a], e = g_offsets[a + 1];

    u64 ac0a = 0, ac0b = 0, ac1a = 0, ac1b = 0, ac2a = 0, ac2b = 0;

    int p = 0, j = 0;
    if (s < e) {
        p = g_pairlist[s];
        j = __ldg(&ind2[2 * p + 1]);
    }

    for (int k = s; k < e; k++) {
        // issue all value loads for current pair (addresses known)
        float4 sv = __ldcs((const float4*)(i1 + (size_t)p * NPROP) + lane);
        const float4* pxj = (const float4*)(px + (size_t)j * 3 * NPROP);
        float4 p0 = __ldg(pxj + lane);
        float4 p1 = __ldg(pxj + 32 + lane);
        float4 p2 = __ldg(pxj + 64 + lane);
        float d0 = __ldg(&diff[3 * p + 0]);
        float d1 = __ldg(&diff[3 * p + 1]);
        float d2 = __ldg(&diff[3 * p + 2]);
        float4* op = (float4*)(ix + (size_t)p * 3 * NPROP);

        // prefetch next pair's index chain while values are in flight
        if (k + 1 < e) {
            p = g_pairlist[k + 1];
            j = __ldg(&ind2[2 * p + 1]);
        }

        u64 sva = pk2(sv.x, sv.y), svb = pk2(sv.z, sv.w);
        u64 d0d = pk2(d0, d0), d1d = pk2(d1, d1), d2d = pk2(d2, d2);

        u64 v0a = mul2(add2(pk2(p0.x, p0.y), d0d), sva);
        u64 v0b = mul2(add2(pk2(p0.z, p0.w), d0d), svb);
        u64 v1a = mul2(add2(pk2(p1.x, p1.y), d1d), sva);
        u64 v1b = mul2(add2(pk2(p1.z, p1.w), d1d), svb);
        u64 v2a = mul2(add2(pk2(p2.x, p2.y), d2d), sva);
        u64 v2b = mul2(add2(pk2(p2.z, p2.w), d2d), svb);

        float4 w0, w1, w2;
        upk2(v0a, w0.x, w0.y); upk2(v0b, w0.z, w0.w);
        upk2(v1a, w1.x, w1.y); upk2(v1b, w1.z, w1.w);
        upk2(v2a, w2.x, w2.y); upk2(v2b, w2.z, w2.w);
        __stcs(op + lane,      w0);
        __stcs(op + 32 + lane, w1);
        __stcs(op + 64 + lane, w2);

        ac0a = add2(ac0a, v0a); ac0b = add2(ac0b, v0b);
        ac1a = add2(ac1a, v1a); ac1b = add2(ac1b, v1b);
        ac2a = add2(ac2a, v2a); ac2b = add2(ac2b, v2b);
    }

    float4 o0, o1, o2;
    upk2(ac0a, o0.x, o0.y); upk2(ac0b, o0.z, o0.w);
    upk2(ac1a, o1.x, o1.y); upk2(ac1b, o1.z, o1.w);
    upk2(ac2a, o2.x, o2.y); upk2(ac2b, o2.z, o2.w);
    float4* ap = (float4*)(g_pxacc + (size_t)a * 3 * NPROP);
    ap[lane]      = o0;
    ap[32 + lane] = o1;
    ap[64 + lane] = o2;
}

// ---------------- K5: px_new = acc @ w_pp, dotted = sum_x px_new^2 --------
// q-split: grid.y selects a 64-wide half of q. Shared = 32KB w-slice + 8KB
// acc = 40KB (no opt-in). Inner loop: 3 fma.rn.f32x2 (fma pipe) + 3 dup movs
// (alu pipe, overlapped) + 2 LDS per c-step.
__global__ void __launch_bounds__(128) k_gemm(
        const float* __restrict__ w,
        float*       __restrict__ pxnew,
        float*       __restrict__ dotted) {
    __shared__ float  sw[128 * 64];           // 32KB: w[:, qh*64 .. qh*64+63]
    __shared__ float4 sacc[4][NPROP];         // 8KB: per-warp acc, [c]={x0,x1,x2,_}

    int tid = threadIdx.x, wd = tid >> 5, lane = tid & 31;
    int qh = blockIdx.y;                      // 0 or 1

    for (int i = tid; i < 2048; i += 128) {
        int c = i >> 4, f4 = i & 15;
        ((float4*)sw)[i] = __ldg((const float4*)(w + (size_t)c * NPROP + qh * 64) + f4);
    }
    __syncthreads();

    const u64* sw2 = (const u64*)sw;          // float2 per lane per c

    int abase = blockIdx.x * 32 + wd * 8;
    for (int t = 0; t < 8; t++) {
        int a = abase + t;
        if (a >= N_ATOMS) break;
        const float* ap = g_pxacc + (size_t)a * 3 * NPROP;
#pragma unroll
        for (int r = 0; r < 4; r++) {
            int c = lane + 32 * r;
            sacc[wd][c] = make_float4(ap[c], ap[NPROP + c], ap[2 * NPROP + c], 0.f);
        }
        __syncwarp();

        u64 o0 = 0, o1 = 0, o2 = 0;
#pragma unroll 8
        for (int c = 0; c < NPROP; c++) {
            u64 wv = sw2[c * 32 + lane];
            float4 av = sacc[wd][c];
            o0 = fma2(pk2(av.x, av.x), wv, o0);
            o1 = fma2(pk2(av.y, av.y), wv, o1);
            o2 = fma2(pk2(av.z, av.z), wv, o2);
        }

        float* pn = pxnew + (size_t)a * 3 * NPROP + qh * 64;
        ((u64*)pn)[lane]                 = o0;
        ((u64*)(pn + NPROP))[lane]       = o1;
        ((u64*)(pn + 2 * NPROP))[lane]   = o2;

        u64 dv = add2(add2(mul2(o0, o0), mul2(o1, o1)), mul2(o2, o2));
        ((u64*)(dotted + (size_t)a * NPROP + qh * 64))[lane] = dv;
        __syncwarp();
    }
}

// ---------------- launch ----------------
extern "C" void kernel_launch(void* const* d_in, const int* in_sizes, int n_in,
                              void* d_out, int out_size) {
    const int*   ind2 = (const int*)  d_in[0];
    const float* px   = (const float*)d_in[1];
    const float* i1   = (const float*)d_in[2];
    const float* diff = (const float*)d_in[3];
    const float* w    = (const float*)d_in[4];

    float* out   = (float*)d_out;
    float* pxnew = out;                                  // 10000*3*128
    float* ixo   = out + 3840000LL;                      // 250000*3*128
    float* dot   = out + 99840000LL;                     // 10000*128

    k_init   <<<(N_ATOMS + 255) / 256, 256>>>();
    k_hist   <<<(N_PAIRS + 255) / 256, 256>>>(ind2);
    k_scan   <<<1, 1024>>>();
    k_scatter<<<(N_PAIRS + 255) / 256, 256>>>(ind2);
    k_sort   <<<(N_ATOMS + 127) / 128, 128>>>();
    k_accum  <<<N_ATOMS / 4, 128>>>(ind2, px, i1, diff, ixo);

    dim3 gg((N_ATOMS + 31) / 32, 2);
    k_gemm   <<<gg, 128>>>(w, pxnew, dot);
}

// round 4
// speedup vs baseline: 1.1761x; 1.1761x over previous
#include <cuda_runtime.h>
#include <cuda_bf16.h>
#include <cstdint>

#define N_ATOMS 10000
#define N_PAIRS 250000
#define NPROP   128

// ---------------- device scratch (static, allocation-free) ----------------
__device__ int   g_counts[N_ATOMS];
__device__ int   g_cursor[N_ATOMS];
__device__ int   g_offsets[N_ATOMS + 1];
__device__ int   g_pairlist[N_PAIRS];
__device__ float g_pxacc[(size_t)N_ATOMS * 3 * NPROP];

// ---------------- K0: zero counts / cursors ----------------
__global__ void k_init() {
    int t = blockIdx.x * blockDim.x + threadIdx.x;
    if (t < N_ATOMS) { g_counts[t] = 0; g_cursor[t] = 0; }
}

// ---------------- K1: histogram of ind_i ----------------
__global__ void k_hist(const int* __restrict__ ind2) {
    int p = blockIdx.x * blockDim.x + threadIdx.x;
    if (p < N_PAIRS) atomicAdd(&g_counts[ind2[2 * p]], 1);
}

// ---------------- K2: exclusive scan of counts -> offsets (1 block) -------
__global__ void k_scan() {
    __shared__ int part[1024];
    const int PER = 10;
    int t = threadIdx.x;
    int local[PER];
    int sum = 0;
#pragma unroll
    for (int r = 0; r < PER; r++) {
        int idx = t * PER + r;
        int v = (idx < N_ATOMS) ? g_counts[idx] : 0;
        local[r] = sum;
        sum += v;
    }
    part[t] = sum;
    __syncthreads();
    for (int off = 1; off < 1024; off <<= 1) {
        int v = (t >= off) ? part[t - off] : 0;
        __syncthreads();
        part[t] += v;
        __syncthreads();
    }
    int base = (t > 0) ? part[t - 1] : 0;
#pragma unroll
    for (int r = 0; r < PER; r++) {
        int idx = t * PER + r;
        if (idx < N_ATOMS) g_offsets[idx] = base + local[r];
    }
    if (t == 1023) g_offsets[N_ATOMS] = part[1023];
}

// ---------------- K3: scatter pair ids into CSR ----------------
__global__ void k_scatter(const int* __restrict__ ind2) {
    int p = blockIdx.x * blockDim.x + threadIdx.x;
    if (p < N_PAIRS) {
        int i = ind2[2 * p];
        int pos = atomicAdd(&g_cursor[i], 1);
        g_pairlist[g_offsets[i] + pos] = p;
    }
}

// ---------------- K3b: per-segment sort (deterministic sum order) ---------
// Warp per atom: segment staged to shared, odd-even transposition sort
// (LDS-only compare/swap rounds), one write-back. Global insertion-sort
// fallback only for segments > 96 (probability ~0 at Poisson(25)).
__global__ void __launch_bounds__(128) k_sort() {
    __shared__ int buf[4][96];
    int wd = threadIdx.x >> 5, lane = threadIdx.x & 31;
    int a = blockIdx.x * 4 + wd;
    if (a >= N_ATOMS) return;
    int s = g_offsets[a], e = g_offsets[a + 1];
    int n = e - s;
    if (n <= 1) return;
    if (n <= 96) {
        for (int i = lane; i < n; i += 32) buf[wd][i] = g_pairlist[s + i];
        __syncwarp();
        for (int r = 0; r < n; r++) {
            int start = r & 1;
            for (int i = start + 2 * lane; i + 1 < n; i += 64) {
                int x = buf[wd][i], y = buf[wd][i + 1];
                if (x > y) { buf[wd][i] = y; buf[wd][i + 1] = x; }
            }
            __syncwarp();
        }
        for (int i = lane; i < n; i += 32) g_pairlist[s + i] = buf[wd][i];
    } else if (lane == 0) {
        for (int i = s + 1; i < e; i++) {
            int v = g_pairlist[i];
            int j = i - 1;
            while (j >= s && g_pairlist[j] > v) { g_pairlist[j + 1] = g_pairlist[j]; j--; }
            g_pairlist[j + 1] = v;
        }
    }
}

// ---------------- K4: hot kernel — ix + per-atom segment sum --------------
// (R2 version — best so far.) One warp per atom; lane owns 4 channels.
// ix streamed (__stcs), i1 read-once (__ldcs), px gathered through L2.
__global__ void __launch_bounds__(128) k_accum(
        const int*   __restrict__ ind2,
        const float* __restrict__ px,
        const float* __restrict__ i1,
        const float* __restrict__ diff,
        float*       __restrict__ ix) {
    int wd   = threadIdx.x >> 5;
    int lane = threadIdx.x & 31;
    int a = blockIdx.x * 4 + wd;              // grid = N_ATOMS/4 exactly
    int s = g_offsets[a], e = g_offsets[a + 1];

    float4 a0 = make_float4(0.f, 0.f, 0.f, 0.f);
    float4 a1 = a0, a2 = a0;

    for (int k = s; k < e; k++) {
        int p = g_pairlist[k];
        int j = __ldg(&ind2[2 * p + 1]);
        float4 sv = __ldcs((const float4*)(i1 + (size_t)p * NPROP) + lane);
        float d0 = __ldg(&diff[3 * p + 0]);
        float d1 = __ldg(&diff[3 * p + 1]);
        float d2 = __ldg(&diff[3 * p + 2]);

        const float4* pxj = (const float4*)(px + (size_t)j * 3 * NPROP);
        float4 p0 = __ldg(pxj + lane);
        float4 p1 = __ldg(pxj + 32 + lane);
        float4 p2 = __ldg(pxj + 64 + lane);

        float4 v0, v1, v2;
        v0.x = fmaf(p0.x, sv.x, d0 * sv.x); v0.y = fmaf(p0.y, sv.y, d0 * sv.y);
        v0.z = fmaf(p0.z, sv.z, d0 * sv.z); v0.w = fmaf(p0.w, sv.w, d0 * sv.w);
        v1.x = fmaf(p1.x, sv.x, d1 * sv.x); v1.y = fmaf(p1.y, sv.y, d1 * sv.y);
        v1.z = fmaf(p1.z, sv.z, d1 * sv.z); v1.w = fmaf(p1.w, sv.w, d1 * sv.w);
        v2.x = fmaf(p2.x, sv.x, d2 * sv.x); v2.y = fmaf(p2.y, sv.y, d2 * sv.y);
        v2.z = fmaf(p2.z, sv.z, d2 * sv.z); v2.w = fmaf(p2.w, sv.w, d2 * sv.w);

        float4* op = (float4*)(ix + (size_t)p * 3 * NPROP);
        __stcs(op + lane,      v0);
        __stcs(op + 32 + lane, v1);
        __stcs(op + 64 + lane, v2);

        a0.x += v0.x; a0.y += v0.y; a0.z += v0.z; a0.w += v0.w;
        a1.x += v1.x; a1.y += v1.y; a1.z += v1.z; a1.w += v1.w;
        a2.x += v2.x; a2.y += v2.y; a2.z += v2.z; a2.w += v2.w;
    }

    float4* ap = (float4*)(g_pxacc + (size_t)a * 3 * NPROP);
    ap[lane]      = a0;
    ap[32 + lane] = a1;
    ap[64 + lane] = a2;
}

// ---------------- K5: px_new = acc @ w_pp, dotted = sum_x px_new^2 --------
// (R2 version.) q-split: grid.y selects a 64-wide half of q; 40KB shared.
__global__ void __launch_bounds__(128) k_gemm(
        const float* __restrict__ w,
        float*       __restrict__ pxnew,
        float*       __restrict__ dotted) {
    __shared__ float  sw[128 * 64];           // 32KB: w[:, qh*64 .. qh*64+63]
    __shared__ float4 sacc[4][NPROP];         // 8KB

    int tid = threadIdx.x, wd = tid >> 5, lane = tid & 31;
    int qh = blockIdx.y;

    for (int i = tid; i < 2048; i += 128) {
        int c = i >> 4, f4 = i & 15;
        ((float4*)sw)[i] = __ldg((const float4*)(w + (size_t)c * NPROP + qh * 64) + f4);
    }
    __syncthreads();

    int abase = blockIdx.x * 32 + wd * 8;
    for (int t = 0; t < 8; t++) {
        int a = abase + t;
        if (a >= N_ATOMS) break;
        const float* ap = g_pxacc + (size_t)a * 3 * NPROP;
#pragma unroll
        for (int r = 0; r < 4; r++) {
            int c = lane + 32 * r;
            sacc[wd][c] = make_float4(ap[c], ap[NPROP + c], ap[2 * NPROP + c], 0.f);
        }
        __syncwarp();

        float2 o0 = make_float2(0.f, 0.f), o1 = o0, o2 = o0;
#pragma unroll 8
        for (int c = 0; c < NPROP; c++) {
            float2 wv = ((const float2*)sw)[c * 32 + lane];
            float4 av = sacc[wd][c];
            o0.x = fmaf(av.x, wv.x, o0.x); o0.y = fmaf(av.x, wv.y, o0.y);
            o1.x = fmaf(av.y, wv.x, o1.x); o1.y = fmaf(av.y, wv.y, o1.y);
            o2.x = fmaf(av.z, wv.x, o2.x); o2.y = fmaf(av.z, wv.y, o2.y);
        }

        float* pn = pxnew + (size_t)a * 3 * NPROP + qh * 64;
        ((float2*)pn)[lane]                = o0;
        ((float2*)(pn + NPROP))[lane]      = o1;
        ((float2*)(pn + 2 * NPROP))[lane]  = o2;

        float2 dv;
        dv.x = o0.x * o0.x + o1.x * o1.x + o2.x * o2.x;
        dv.y = o0.y * o0.y + o1.y * o1.y + o2.y * o2.y;
        ((float2*)(dotted + (size_t)a * NPROP + qh * 64))[lane] = dv;
        __syncwarp();
    }
}

// ---------------- launch ----------------
extern "C" void kernel_launch(void* const* d_in, const int* in_sizes, int n_in,
                              void* d_out, int out_size) {
    const int*   ind2 = (const int*)  d_in[0];
    const float* px   = (const float*)d_in[1];
    const float* i1   = (const float*)d_in[2];
    const float* diff = (const float*)d_in[3];
    const float* w    = (const float*)d_in[4];

    float* out   = (float*)d_out;
    float* pxnew = out;                                  // 10000*3*128
    float* ixo   = out + 3840000LL;                      // 250000*3*128
    float* dot   = out + 99840000LL;                     // 10000*128

    k_init   <<<(N_ATOMS + 255) / 256, 256>>>();
    k_hist   <<<(N_PAIRS + 255) / 256, 256>>>(ind2);
    k_scan   <<<1, 1024>>>();
    k_scatter<<<(N_PAIRS + 255) / 256, 256>>>(ind2);
    k_sort   <<<(N_ATOMS + 3) / 4, 128>>>();
    k_accum  <<<N_ATOMS / 4, 128>>>(ind2, px, i1, diff, ixo);

    dim3 gg((N_ATOMS + 31) / 32, 2);
    k_gemm   <<<gg, 128>>>(w, pxnew, dot);
}

// round 5
// speedup vs baseline: 1.1889x; 1.0109x over previous
#include <cuda_runtime.h>
#include <cuda_bf16.h>
#include <cstdint>

#define N_ATOMS 10000
#define N_PAIRS 250000
#define NPROP   128

// ---------------- device scratch (static, allocation-free) ----------------
__device__ int   g_counts[N_ATOMS];
__device__ int   g_cursor[N_ATOMS];
__device__ int   g_offsets[N_ATOMS + 1];
__device__ int   g_pairlist[N_PAIRS];
__device__ float g_pxacc[(size_t)N_ATOMS * 3 * NPROP];

// ---------------- K0: zero counts / cursors ----------------
__global__ void k_init() {
    int t = blockIdx.x * blockDim.x + threadIdx.x;
    if (t < N_ATOMS) { g_counts[t] = 0; g_cursor[t] = 0; }
}

// ---------------- K1: histogram of ind_i ----------------
__global__ void k_hist(const int* __restrict__ ind2) {
    int p = blockIdx.x * blockDim.x + threadIdx.x;
    if (p < N_PAIRS) atomicAdd(&g_counts[ind2[2 * p]], 1);
}

// ---------------- K2: exclusive scan of counts -> offsets (1 block) -------
__global__ void k_scan() {
    __shared__ int part[1024];
    const int PER = 10;
    int t = threadIdx.x;
    int local[PER];
    int sum = 0;
#pragma unroll
    for (int r = 0; r < PER; r++) {
        int idx = t * PER + r;
        int v = (idx < N_ATOMS) ? g_counts[idx] : 0;
        local[r] = sum;
        sum += v;
    }
    part[t] = sum;
    __syncthreads();
    for (int off = 1; off < 1024; off <<= 1) {
        int v = (t >= off) ? part[t - off] : 0;
        __syncthreads();
        part[t] += v;
        __syncthreads();
    }
    int base = (t > 0) ? part[t - 1] : 0;
#pragma unroll
    for (int r = 0; r < PER; r++) {
        int idx = t * PER + r;
        if (idx < N_ATOMS) g_offsets[idx] = base + local[r];
    }
    if (t == 1023) g_offsets[N_ATOMS] = part[1023];
}

// ---------------- K3: scatter pair ids into CSR ----------------
__global__ void k_scatter(const int* __restrict__ ind2) {
    int p = blockIdx.x * blockDim.x + threadIdx.x;
    if (p < N_PAIRS) {
        int i = ind2[2 * p];
        int pos = atomicAdd(&g_cursor[i], 1);
        g_pairlist[g_offsets[i] + pos] = p;
    }
}

// ---------------- K3b: per-segment sort (warp odd-even in shared) ---------
__global__ void __launch_bounds__(128) k_sort() {
    __shared__ int buf[4][96];
    int wd = threadIdx.x >> 5, lane = threadIdx.x & 31;
    int a = blockIdx.x * 4 + wd;
    if (a >= N_ATOMS) return;
    int s = g_offsets[a], e = g_offsets[a + 1];
    int n = e - s;
    if (n <= 1) return;
    if (n <= 96) {
        for (int i = lane; i < n; i += 32) buf[wd][i] = g_pairlist[s + i];
        __syncwarp();
        for (int r = 0; r < n; r++) {
            int start = r & 1;
            for (int i = start + 2 * lane; i + 1 < n; i += 64) {
                int x = buf[wd][i], y = buf[wd][i + 1];
                if (x > y) { buf[wd][i] = y; buf[wd][i + 1] = x; }
            }
            __syncwarp();
        }
        for (int i = lane; i < n; i += 32) g_pairlist[s + i] = buf[wd][i];
    } else if (lane == 0) {
        for (int i = s + 1; i < e; i++) {
            int v = g_pairlist[i];
            int j = i - 1;
            while (j >= s && g_pairlist[j] > v) { g_pairlist[j + 1] = g_pairlist[j]; j--; }
            g_pairlist[j + 1] = v;
        }
    }
}

// ---------------- K4: hot kernel — ix + per-atom segment sum --------------
// One warp per atom. 2-pair unrolled software pipeline: both pairs' value
// loads issued together (2x MLP), next iteration's pairlist/ind2 indices
// prefetched while values are in flight. Scalar FFMA math (R2/R4 form).
__device__ __forceinline__ void pair_body(
        int p, int j, int lane,
        const float* __restrict__ px, const float* __restrict__ i1,
        const float* __restrict__ diff, float* __restrict__ ix,
        float4& a0, float4& a1, float4& a2) {
    float4 sv = __ldcs((const float4*)(i1 + (size_t)p * NPROP) + lane);
    float d0 = __ldg(&diff[3 * p + 0]);
    float d1 = __ldg(&diff[3 * p + 1]);
    float d2 = __ldg(&diff[3 * p + 2]);
    const float4* pxj = (const float4*)(px + (size_t)j * 3 * NPROP);
    float4 p0 = __ldg(pxj + lane);
    float4 p1 = __ldg(pxj + 32 + lane);
    float4 p2 = __ldg(pxj + 64 + lane);

    float4 v0, v1, v2;
    v0.x = fmaf(p0.x, sv.x, d0 * sv.x); v0.y = fmaf(p0.y, sv.y, d0 * sv.y);
    v0.z = fmaf(p0.z, sv.z, d0 * sv.z); v0.w = fmaf(p0.w, sv.w, d0 * sv.w);
    v1.x = fmaf(p1.x, sv.x, d1 * sv.x); v1.y = fmaf(p1.y, sv.y, d1 * sv.y);
    v1.z = fmaf(p1.z, sv.z, d1 * sv.z); v1.w = fmaf(p1.w, sv.w, d1 * sv.w);
    v2.x = fmaf(p2.x, sv.x, d2 * sv.x); v2.y = fmaf(p2.y, sv.y, d2 * sv.y);
    v2.z = fmaf(p2.z, sv.z, d2 * sv.z); v2.w = fmaf(p2.w, sv.w, d2 * sv.w);

    float4* op = (float4*)(ix + (size_t)p * 3 * NPROP);
    __stcs(op + lane,      v0);
    __stcs(op + 32 + lane, v1);
    __stcs(op + 64 + lane, v2);

    a0.x += v0.x; a0.y += v0.y; a0.z += v0.z; a0.w += v0.w;
    a1.x += v1.x; a1.y += v1.y; a1.z += v1.z; a1.w += v1.w;
    a2.x += v2.x; a2.y += v2.y; a2.z += v2.z; a2.w += v2.w;
}

__global__ void __launch_bounds__(128) k_accum(
        const int*   __restrict__ ind2,
        const float* __restrict__ px,
        const float* __restrict__ i1,
        const float* __restrict__ diff,
        float*       __restrict__ ix) {
    int wd   = threadIdx.x >> 5;
    int lane = threadIdx.x & 31;
    int a = blockIdx.x * 4 + wd;              // grid = N_ATOMS/4 exactly
    int s = g_offsets[a], e = g_offsets[a + 1];

    float4 a0 = make_float4(0.f, 0.f, 0.f, 0.f);
    float4 a1 = a0, a2 = a0;

    // prime the index pipeline (2 ahead)
    int pA = 0, jA = 0, pB = 0, jB = 0;
    if (s < e)     { pA = g_pairlist[s];     jA = __ldg(&ind2[2 * pA + 1]); }
    if (s + 1 < e) { pB = g_pairlist[s + 1]; jB = __ldg(&ind2[2 * pB + 1]); }

    int k = s;
    for (; k + 1 < e; k += 2) {
        int pa = pA, ja = jA, pb = pB, jb = jB;
        // prefetch next pair of indices while values load below
        if (k + 2 < e) { pA = g_pairlist[k + 2]; jA = __ldg(&ind2[2 * pA + 1]); }
        if (k + 3 < e) { pB = g_pairlist[k + 3]; jB = __ldg(&ind2[2 * pB + 1]); }

        // two independent pair bodies -> 2x loads in flight
        pair_body(pa, ja, lane, px, i1, diff, ix, a0, a1, a2);
        pair_body(pb, jb, lane, px, i1, diff, ix, a0, a1, a2);
    }
    if (k < e) {
        pair_body(pA, jA, lane, px, i1, diff, ix, a0, a1, a2);
    }

    float4* ap = (float4*)(g_pxacc + (size_t)a * 3 * NPROP);
    ap[lane]      = a0;
    ap[32 + lane] = a1;
    ap[64 + lane] = a2;
}

// ---------------- K5: px_new = acc @ w_pp, dotted = sum_x px_new^2 --------
// (R2/R4 version.) q-split: grid.y selects a 64-wide half of q; 40KB shared.
__global__ void __launch_bounds__(128) k_gemm(
        const float* __restrict__ w,
        float*       __restrict__ pxnew,
        float*       __restrict__ dotted) {
    __shared__ float  sw[128 * 64];           // 32KB: w[:, qh*64 .. qh*64+63]
    __shared__ float4 sacc[4][NPROP];         // 8KB

    int tid = threadIdx.x, wd = tid >> 5, lane = tid & 31;
    int qh = blockIdx.y;

    for (int i = tid; i < 2048; i += 128) {
        int c = i >> 4, f4 = i & 15;
        ((float4*)sw)[i] = __ldg((const float4*)(w + (size_t)c * NPROP + qh * 64) + f4);
    }
    __syncthreads();

    int abase = blockIdx.x * 32 + wd * 8;
    for (int t = 0; t < 8; t++) {
        int a = abase + t;
        if (a >= N_ATOMS) break;
        const float* ap = g_pxacc + (size_t)a * 3 * NPROP;
#pragma unroll
        for (int r = 0; r < 4; r++) {
            int c = lane + 32 * r;
            sacc[wd][c] = make_float4(ap[c], ap[NPROP + c], ap[2 * NPROP + c], 0.f);
        }
        __syncwarp();

        float2 o0 = make_float2(0.f, 0.f), o1 = o0, o2 = o0;
#pragma unroll 8
        for (int c = 0; c < NPROP; c++) {
            float2 wv = ((const float2*)sw)[c * 32 + lane];
            float4 av = sacc[wd][c];
            o0.x = fmaf(av.x, wv.x, o0.x); o0.y = fmaf(av.x, wv.y, o0.y);
            o1.x = fmaf(av.y, wv.x, o1.x); o1.y = fmaf(av.y, wv.y, o1.y);
            o2.x = fmaf(av.z, wv.x, o2.x); o2.y = fmaf(av.z, wv.y, o2.y);
        }

        float* pn = pxnew + (size_t)a * 3 * NPROP + qh * 64;
        ((float2*)pn)[lane]                = o0;
        ((float2*)(pn + NPROP))[lane]      = o1;
        ((float2*)(pn + 2 * NPROP))[lane]  = o2;

        float2 dv;
        dv.x = o0.x * o0.x + o1.x * o1.x + o2.x * o2.x;
        dv.y = o0.y * o0.y + o1.y * o1.y + o2.y * o2.y;
        ((float2*)(dotted + (size_t)a * NPROP + qh * 64))[lane] = dv;
        __syncwarp();
    }
}

// ---------------- launch ----------------
extern "C" void kernel_launch(void* const* d_in, const int* in_sizes, int n_in,
                              void* d_out, int out_size) {
    const int*   ind2 = (const int*)  d_in[0];
    const float* px   = (const float*)d_in[1];
    const float* i1   = (const float*)d_in[2];
    const float* diff = (const float*)d_in[3];
    const float* w    = (const float*)d_in[4];

    float* out   = (float*)d_out;
    float* pxnew = out;                                  // 10000*3*128
    float* ixo   = out + 3840000LL;                      // 250000*3*128
    float* dot   = out + 99840000LL;                     // 10000*128

    k_init   <<<(N_ATOMS + 255) / 256, 256>>>();
    k_hist   <<<(N_PAIRS + 255) / 256, 256>>>(ind2);
    k_scan   <<<1, 1024>>>();
    k_scatter<<<(N_PAIRS + 255) / 256, 256>>>(ind2);
    k_sort   <<<(N_ATOMS + 3) / 4, 128>>>();
    k_accum  <<<N_ATOMS / 4, 128>>>(ind2, px, i1, diff, ixo);

    dim3 gg((N_ATOMS + 31) / 32, 2);
    k_gemm   <<<gg, 128>>>(w, pxnew, dot);
}